// round 11
// baseline (speedup 1.0000x reference)
#include <cuda_runtime.h>
#include <cstdint>

#define SEQ   8192
#define DIM   128
#define GATES 512
#define TOK_PER_BLK 8
#define HALF  64
#define LSTM_THREADS 256
#define ARRIVES 64

typedef unsigned long long u64;

// Scratch (device globals; no runtime allocation allowed)
__device__ float g_z[SEQ * DIM];        // expert-linear output, 4 MB
__device__ float g_xg[SEQ * GATES];     // precomputed input-gate contributions, 16 MB

// ---------------------------------------------------------------------------
// f32x2 packed helpers (FFMA2 only reachable via PTX fma.rn.f32x2)
// ---------------------------------------------------------------------------
__device__ __forceinline__ u64 fma2(u64 a, u64 b, u64 c) {
    u64 d;
    asm("fma.rn.f32x2 %0, %1, %2, %3;" : "=l"(d) : "l"(a), "l"(b), "l"(c));
    return d;
}
__device__ __forceinline__ u64 add2(u64 a, u64 b) {
    u64 d;
    asm("add.rn.f32x2 %0, %1, %2;" : "=l"(d) : "l"(a), "l"(b));
    return d;
}
__device__ __forceinline__ u64 pack2(float lo, float hi) {
    u64 p;
    asm("mov.b64 %0, {%1, %2};" : "=l"(p) : "r"(__float_as_uint(lo)), "r"(__float_as_uint(hi)));
    return p;
}
__device__ __forceinline__ float hsum2(u64 p) {
    unsigned int lo, hi;
    asm("mov.b64 {%0, %1}, %2;" : "=r"(lo), "=r"(hi) : "l"(p));
    return __uint_as_float(lo) + __uint_as_float(hi);
}

__device__ __forceinline__ float fast_sigmoid(float x) {
    return 1.0f / (1.0f + __expf(-x));
}
__device__ __forceinline__ float fast_tanh(float x) {
    // exact at saturation: exp(2x)->inf gives 1, ->0 gives -1
    return 1.0f - 2.0f / (__expf(2.0f * x) + 1.0f);
}

// ---------------------------------------------------------------------------
// Cluster / mbarrier primitives
// ---------------------------------------------------------------------------
__device__ __forceinline__ uint32_t smem_u32(const void* p) {
    uint32_t a;
    asm("{ .reg .u64 t; cvta.to.shared.u64 t, %1; cvt.u32.u64 %0, t; }"
        : "=r"(a) : "l"(p));
    return a;
}
__device__ __forceinline__ uint32_t ctarank() {
    uint32_t r;
    asm("mov.u32 %0, %%cluster_ctarank;" : "=r"(r));
    return r;
}
__device__ __forceinline__ uint32_t mapa_u32(uint32_t addr, uint32_t rank) {
    uint32_t r;
    asm("mapa.shared::cluster.u32 %0, %1, %2;" : "=r"(r) : "r"(addr), "r"(rank));
    return r;
}
__device__ __forceinline__ void st_cluster_f32(uint32_t addr, float v) {
    asm volatile("st.shared::cluster.b32 [%0], %1;"
                 :: "r"(addr), "r"(__float_as_uint(v)) : "memory");
}
__device__ __forceinline__ void mbar_init(uint32_t bar, uint32_t cnt) {
    asm volatile("mbarrier.init.shared.b64 [%0], %1;" :: "r"(bar), "r"(cnt) : "memory");
}
// release.cluster: orders THIS thread's preceding st.shared::cluster before the arrival
__device__ __forceinline__ void mbar_arrive_release_cluster(uint32_t bar) {
    asm volatile("mbarrier.arrive.release.cluster.shared::cluster.b64 _, [%0];"
                 :: "r"(bar) : "memory");
}
__device__ __forceinline__ void mbar_wait_parity_cluster(uint32_t bar, uint32_t parity) {
    uint32_t done;
    do {
        asm volatile(
            "{\n\t.reg .pred p;\n\t"
            "mbarrier.try_wait.parity.acquire.cluster.shared::cta.b64 p, [%1], %2;\n\t"
            "selp.b32 %0, 1, 0, p;\n\t}"
            : "=r"(done) : "r"(bar), "r"(parity) : "memory");
    } while (!done);
}
__device__ __forceinline__ void cluster_sync() {
    asm volatile("barrier.cluster.arrive.aligned;" ::: "memory");
    asm volatile("barrier.cluster.wait.aligned;" ::: "memory");
}

// ---------------------------------------------------------------------------
// Phase A: z[s,i] = sum_j W_exp[e(s),i,j]*embs[s,j] + b_exp[e(s),i]
// ---------------------------------------------------------------------------
__global__ void k_expert(const float* __restrict__ embs,
                         const int* __restrict__ pos_ids,
                         const float* __restrict__ W_exp,
                         const float* __restrict__ b_exp) {
    __shared__ float e_s[DIM];
    int s = blockIdx.x;
    int i = threadIdx.x;
    e_s[i] = embs[s * DIM + i];
    __syncthreads();
    int e = pos_ids[s];
    const float* Wr = W_exp + ((size_t)e * DIM + i) * DIM;
    float acc = b_exp[e * DIM + i];
#pragma unroll
    for (int q = 0; q < DIM / 4; q++) {
        float4 w4 = *reinterpret_cast<const float4*>(Wr + 4 * q);
        acc = fmaf(w4.x, e_s[4 * q + 0], acc);
        acc = fmaf(w4.y, e_s[4 * q + 1], acc);
        acc = fmaf(w4.z, e_s[4 * q + 2], acc);
        acc = fmaf(w4.w, e_s[4 * q + 3], acc);
    }
    g_z[s * DIM + i] = acc;
}

// ---------------------------------------------------------------------------
// Phase B: xg[s,t] = sum_j z[s,j]*W_ih[t,j] + b_ih[t] + b_hh[t]
// ---------------------------------------------------------------------------
__global__ void k_inproj(const float* __restrict__ W_ih,
                         const float* __restrict__ b_ih,
                         const float* __restrict__ b_hh) {
    __shared__ float z_s[TOK_PER_BLK][DIM];
    int t = threadIdx.x;
    int tok0 = blockIdx.x * TOK_PER_BLK;
    for (int i = t; i < TOK_PER_BLK * DIM; i += GATES)
        z_s[i / DIM][i % DIM] = g_z[tok0 * DIM + i];
    __syncthreads();
    float acc[TOK_PER_BLK];
    float b = b_ih[t] + b_hh[t];
#pragma unroll
    for (int r = 0; r < TOK_PER_BLK; r++) acc[r] = b;
    const float* Wr = W_ih + t * DIM;
#pragma unroll
    for (int q = 0; q < DIM / 4; q++) {
        float4 w4 = *reinterpret_cast<const float4*>(Wr + 4 * q);
#pragma unroll
        for (int r = 0; r < TOK_PER_BLK; r++) {
            acc[r] = fmaf(w4.x, z_s[r][4 * q + 0], acc[r]);
            acc[r] = fmaf(w4.y, z_s[r][4 * q + 1], acc[r]);
            acc[r] = fmaf(w4.z, z_s[r][4 * q + 2], acc[r]);
            acc[r] = fmaf(w4.w, z_s[r][4 * q + 3], acc[r]);
        }
    }
#pragma unroll
    for (int r = 0; r < TOK_PER_BLK; r++)
        g_xg[(size_t)(tok0 + r) * GATES + t] = acc[r];
}

// ---------------------------------------------------------------------------
// Phase C+D: LSTM scan on a 2-CTA cluster, partitioned by h-DIMENSION.
// CTA rank r owns h dims [64r, 64r+64) with ALL FOUR gates (4x64 = 256 rows,
// one W_hh row per thread, fully register-resident). c/h update is local;
// only the 64-float h half crosses to the peer (st.shared::cluster, sent by
// the thread that computes it). Next step's GEMV accumulates over the OWN
// h half first, then waits the mbarrier, then the peer half — the DSMEM
// transit overlaps the own-half GEMV.
// Thread t: gate type gt=t/64 (0=i,1=f,2=g,3=o), dim j = 64r + (t%64),
// global gate row = gt*128 + j.
// ---------------------------------------------------------------------------
__global__ __cluster_dims__(2, 1, 1) __launch_bounds__(LSTM_THREADS, 1)
void k_lstm2(const float* __restrict__ W_hh, float* __restrict__ out) {
    __shared__ __align__(16) float h_f[2][DIM];      // full h, double-buffered
    __shared__ __align__(16) float gate_s[LSTM_THREADS];
    __shared__ __align__(8) u64 mbars[2];

    int t = threadIdx.x;
    uint32_t rank = ctarank();
    uint32_t peer = rank ^ 1u;
    int gt  = t >> 6;                 // gate type
    int dl  = t & 63;                 // dim within own half
    int dim = (int)rank * HALF + dl;  // owned h dim (for t<64 update duty)
    int grow = gt * DIM + dim;        // global gate row for this thread
    bool is_g = (gt == 2);

    // W_hh row fully in registers (64 u64 = 128 regs)
    u64 w2[64];
    const u64* Wr = reinterpret_cast<const u64*>(W_hh + (size_t)grow * DIM);
#pragma unroll
    for (int j = 0; j < 64; j++) w2[j] = Wr[j];

    uint32_t bar0 = smem_u32(&mbars[0]);
    uint32_t bar1 = smem_u32(&mbars[1]);
    if (t == 0) { mbar_init(bar0, ARRIVES); mbar_init(bar1, ARRIVES); }
    if (t < DIM) h_f[0][t] = 0.0f;    // step 0 reads buffer 0: all zeros
    __syncthreads();
    cluster_sync();   // barriers initialized before any remote traffic

    // Remote addrs (t<64 senders): peer's h_f[b][my dim], peer's mbars[b]
    uint32_t rh0 = mapa_u32(smem_u32(&h_f[0][dim]), peer);
    uint32_t rh1 = mapa_u32(smem_u32(&h_f[1][dim]), peer);
    uint32_t rb0 = mapa_u32(bar0, peer);
    uint32_t rb1 = mapa_u32(bar1, peer);

    // ulonglong2 entry k covers h cols 4k..4k+3. Own entries: [16*rank, +16).
    int own0  = 16 * (int)rank;
    int peer0 = 16 * (int)peer;

    float c = 0.0f;
    float hmax = -3.0e38f;
    float xg_next = g_xg[grow];       // step 0's input contribution

    for (int step = 0; step < SEQ; step++) {
        int buf = step & 1;
        u64 a0 = pack2(xg_next, 0.0f);
        u64 a1 = pack2(0.0f, 0.0f);
        u64 a2 = a1, a3 = a1;
        int nstep = min(step + 1, SEQ - 1);
        xg_next = __ldg(&g_xg[(size_t)nstep * GATES + grow]);

        const ulonglong2* hh = reinterpret_cast<const ulonglong2*>(h_f[buf]);
        // ---- own half: no wait needed ----
#pragma unroll
        for (int k = 0; k < 8; k++) {
            ulonglong2 p0 = hh[own0 + 2 * k];
            ulonglong2 p1 = hh[own0 + 2 * k + 1];
            a0 = fma2(w2[2 * (own0 + 2 * k) + 0], p0.x, a0);
            a1 = fma2(w2[2 * (own0 + 2 * k) + 1], p0.y, a1);
            a2 = fma2(w2[2 * (own0 + 2 * k) + 2], p1.x, a2);
            a3 = fma2(w2[2 * (own0 + 2 * k) + 3], p1.y, a3);
        }
        // ---- wait for peer's half of h (skipped at step 0: buffer zeroed) ----
        if (step > 0)
            mbar_wait_parity_cluster(buf ? bar1 : bar0, ((step - 1) >> 1) & 1);
        // ---- peer half ----
#pragma unroll
        for (int k = 0; k < 8; k++) {
            ulonglong2 p0 = hh[peer0 + 2 * k];
            ulonglong2 p1 = hh[peer0 + 2 * k + 1];
            a0 = fma2(w2[2 * (peer0 + 2 * k) + 0], p0.x, a0);
            a1 = fma2(w2[2 * (peer0 + 2 * k) + 1], p0.y, a1);
            a2 = fma2(w2[2 * (peer0 + 2 * k) + 2], p1.x, a2);
            a3 = fma2(w2[2 * (peer0 + 2 * k) + 3], p1.y, a3);
        }
        float v = hsum2(add2(add2(a0, a1), add2(a2, a3)));
        gate_s[t] = is_g ? fast_tanh(v) : fast_sigmoid(v);
        __syncthreads();                     // all 256 gates staged (local)

        if (t < HALF) {
            float iv = gate_s[t];            // i for dim
            float fv = gate_s[HALF + t];     // f
            float gg = gate_s[2 * HALF + t]; // g
            float ov = gate_s[3 * HALF + t]; // o
            c = fmaf(fv, c, iv * gg);
            float h = ov * fast_tanh(c);
            hmax = fmaxf(hmax, h);
            int nb = buf ^ 1;                // next step's buffer
            h_f[nb][dim] = h;                // local own half
            st_cluster_f32(nb ? rh1 : rh0, h);          // ship to peer
            mbar_arrive_release_cluster(nb ? rb1 : rb0); // signal peer
        }
        __syncthreads();                     // own-half h visible to all locally
    }

    if (t < HALF) out[dim] = hmax;           // each CTA writes its 64 dims
    cluster_sync();   // keep peer smem alive until all remote ops drained
}

// ---------------------------------------------------------------------------
extern "C" void kernel_launch(void* const* d_in, const int* in_sizes, int n_in,
                              void* d_out, int out_size) {
    const float* embs  = (const float*)d_in[0];
    const int*   pos   = (const int*)  d_in[1];
    const float* W_exp = (const float*)d_in[2];
    const float* b_exp = (const float*)d_in[3];
    const float* W_ih  = (const float*)d_in[4];
    const float* W_hh  = (const float*)d_in[5];
    const float* b_ih  = (const float*)d_in[6];
    const float* b_hh  = (const float*)d_in[7];
    float* out = (float*)d_out;

    k_expert<<<SEQ, DIM>>>(embs, pos, W_exp, b_exp);
    k_inproj<<<SEQ / TOK_PER_BLK, GATES>>>(W_ih, b_ih, b_hh);
    k_lstm2<<<2, LSTM_THREADS>>>(W_hh, out);
}

// round 14
// speedup vs baseline: 1.7320x; 1.7320x over previous
#include <cuda_runtime.h>
#include <cstdint>

#define SEQ   8192
#define DIM   128
#define GATES 512
#define TOK_PER_BLK 8
#define HALF  64
#define LSTM_THREADS 256
#define ARRIVES 64

typedef unsigned long long u64;

// Scratch (device globals; no runtime allocation allowed)
__device__ float g_z[SEQ * DIM];        // expert-linear output, 4 MB
__device__ float g_xg[SEQ * GATES];     // precomputed input-gate contributions, 16 MB

// ---------------------------------------------------------------------------
// f32x2 packed helpers (FFMA2 only reachable via PTX fma.rn.f32x2)
// ---------------------------------------------------------------------------
__device__ __forceinline__ u64 fma2(u64 a, u64 b, u64 c) {
    u64 d;
    asm("fma.rn.f32x2 %0, %1, %2, %3;" : "=l"(d) : "l"(a), "l"(b), "l"(c));
    return d;
}
__device__ __forceinline__ u64 add2(u64 a, u64 b) {
    u64 d;
    asm("add.rn.f32x2 %0, %1, %2;" : "=l"(d) : "l"(a), "l"(b));
    return d;
}
__device__ __forceinline__ u64 pack2(float lo, float hi) {
    u64 p;
    asm("mov.b64 %0, {%1, %2};" : "=l"(p) : "r"(__float_as_uint(lo)), "r"(__float_as_uint(hi)));
    return p;
}
__device__ __forceinline__ float hsum2(u64 p) {
    unsigned int lo, hi;
    asm("mov.b64 {%0, %1}, %2;" : "=r"(lo), "=r"(hi) : "l"(p));
    return __uint_as_float(lo) + __uint_as_float(hi);
}

__device__ __forceinline__ float fast_tanh(float x) {
    // exact at saturation: exp(2x)->inf gives 1, ->0 gives -1
    return 1.0f - 2.0f / (__expf(2.0f * x) + 1.0f);
}

// ---------------------------------------------------------------------------
// Cluster / mbarrier primitives
// ---------------------------------------------------------------------------
__device__ __forceinline__ uint32_t smem_u32(const void* p) {
    uint32_t a;
    asm("{ .reg .u64 t; cvta.to.shared.u64 t, %1; cvt.u32.u64 %0, t; }"
        : "=r"(a) : "l"(p));
    return a;
}
__device__ __forceinline__ uint32_t ctarank() {
    uint32_t r;
    asm("mov.u32 %0, %%cluster_ctarank;" : "=r"(r));
    return r;
}
__device__ __forceinline__ uint32_t mapa_u32(uint32_t addr, uint32_t rank) {
    uint32_t r;
    asm("mapa.shared::cluster.u32 %0, %1, %2;" : "=r"(r) : "r"(addr), "r"(rank));
    return r;
}
__device__ __forceinline__ void st_cluster_f32(uint32_t addr, float v) {
    asm volatile("st.shared::cluster.b32 [%0], %1;"
                 :: "r"(addr), "r"(__float_as_uint(v)) : "memory");
}
__device__ __forceinline__ void mbar_init(uint32_t bar, uint32_t cnt) {
    asm volatile("mbarrier.init.shared.b64 [%0], %1;" :: "r"(bar), "r"(cnt) : "memory");
}
// release.cluster: orders THIS thread's preceding st.shared::cluster before the arrival
__device__ __forceinline__ void mbar_arrive_release_cluster(uint32_t bar) {
    asm volatile("mbarrier.arrive.release.cluster.shared::cluster.b64 _, [%0];"
                 :: "r"(bar) : "memory");
}
__device__ __forceinline__ void mbar_wait_parity_cluster(uint32_t bar, uint32_t parity) {
    uint32_t done;
    do {
        asm volatile(
            "{\n\t.reg .pred p;\n\t"
            "mbarrier.try_wait.parity.acquire.cluster.shared::cta.b64 p, [%1], %2;\n\t"
            "selp.b32 %0, 1, 0, p;\n\t}"
            : "=r"(done) : "r"(bar), "r"(parity) : "memory");
    } while (!done);
}
__device__ __forceinline__ void cluster_sync() {
    asm volatile("barrier.cluster.arrive.aligned;" ::: "memory");
    asm volatile("barrier.cluster.wait.aligned;" ::: "memory");
}

// ---------------------------------------------------------------------------
// Phase A: z[s,i] = sum_j W_exp[e(s),i,j]*embs[s,j] + b_exp[e(s),i]
// ---------------------------------------------------------------------------
__global__ void k_expert(const float* __restrict__ embs,
                         const int* __restrict__ pos_ids,
                         const float* __restrict__ W_exp,
                         const float* __restrict__ b_exp) {
    __shared__ float e_s[DIM];
    int s = blockIdx.x;
    int i = threadIdx.x;
    e_s[i] = embs[s * DIM + i];
    __syncthreads();
    int e = pos_ids[s];
    const float* Wr = W_exp + ((size_t)e * DIM + i) * DIM;
    float acc = b_exp[e * DIM + i];
#pragma unroll
    for (int q = 0; q < DIM / 4; q++) {
        float4 w4 = *reinterpret_cast<const float4*>(Wr + 4 * q);
        acc = fmaf(w4.x, e_s[4 * q + 0], acc);
        acc = fmaf(w4.y, e_s[4 * q + 1], acc);
        acc = fmaf(w4.z, e_s[4 * q + 2], acc);
        acc = fmaf(w4.w, e_s[4 * q + 3], acc);
    }
    g_z[s * DIM + i] = acc;
}

// ---------------------------------------------------------------------------
// Phase B: xg[s,t] = sum_j z[s,j]*W_ih[t,j] + b_ih[t] + b_hh[t]
// ---------------------------------------------------------------------------
__global__ void k_inproj(const float* __restrict__ W_ih,
                         const float* __restrict__ b_ih,
                         const float* __restrict__ b_hh) {
    __shared__ float z_s[TOK_PER_BLK][DIM];
    int t = threadIdx.x;
    int tok0 = blockIdx.x * TOK_PER_BLK;
    for (int i = t; i < TOK_PER_BLK * DIM; i += GATES)
        z_s[i / DIM][i % DIM] = g_z[tok0 * DIM + i];
    __syncthreads();
    float acc[TOK_PER_BLK];
    float b = b_ih[t] + b_hh[t];
#pragma unroll
    for (int r = 0; r < TOK_PER_BLK; r++) acc[r] = b;
    const float* Wr = W_ih + t * DIM;
#pragma unroll
    for (int q = 0; q < DIM / 4; q++) {
        float4 w4 = *reinterpret_cast<const float4*>(Wr + 4 * q);
#pragma unroll
        for (int r = 0; r < TOK_PER_BLK; r++) {
            acc[r] = fmaf(w4.x, z_s[r][4 * q + 0], acc[r]);
            acc[r] = fmaf(w4.y, z_s[r][4 * q + 1], acc[r]);
            acc[r] = fmaf(w4.z, z_s[r][4 * q + 2], acc[r]);
            acc[r] = fmaf(w4.w, z_s[r][4 * q + 3], acc[r]);
        }
    }
#pragma unroll
    for (int r = 0; r < TOK_PER_BLK; r++)
        g_xg[(size_t)(tok0 + r) * GATES + t] = acc[r];
}

// ---------------------------------------------------------------------------
// Phase C+D: LSTM scan on a 2-CTA cluster, partitioned by h-DIMENSION.
// CTA rank r owns h dims [64r, 64r+64) with all 4 gates. Thread t handles
// dim j = 64r + (t>>2), gate k = t&3 (i,f,g,o). W row fully register-
// resident with COMPILE-TIME indices only (no spill). Per step:
//   wait peer-h mbarrier (parity, double-buffered) -> full-128 GEMV ->
//   activation (unified MUFU path) -> 4 warp shuffles gather the dim's
//   gates -> redundant c/h in 4 lanes -> lane k==0 stores h locally and
//   st.shared::cluster to peer + arrive -> one __syncthreads.
// ---------------------------------------------------------------------------
__global__ __cluster_dims__(2, 1, 1) __launch_bounds__(LSTM_THREADS, 1)
void k_lstm2(const float* __restrict__ W_hh, float* __restrict__ out) {
    __shared__ __align__(16) float h_f[2][DIM];      // full h, double-buffered
    __shared__ __align__(8) u64 mbars[2];

    int t = threadIdx.x;
    uint32_t rank = ctarank();
    uint32_t peer = rank ^ 1u;
    int k   = t & 3;                        // gate type: 0=i,1=f,2=g,3=o
    int dim = (int)rank * HALF + (t >> 2);  // owned h dim
    int grow = k * DIM + dim;               // global gate row
    bool is_g = (k == 2);
    int lane = t & 31;
    int base = lane & ~3;                   // first lane of this dim's group

    // W_hh row fully in registers (64 u64 = 128 regs), compile-time indexed
    u64 w2[64];
    const u64* Wr = reinterpret_cast<const u64*>(W_hh + (size_t)grow * DIM);
#pragma unroll
    for (int j = 0; j < 64; j++) w2[j] = Wr[j];

    uint32_t bar0 = smem_u32(&mbars[0]);
    uint32_t bar1 = smem_u32(&mbars[1]);
    if (t == 0) { mbar_init(bar0, ARRIVES); mbar_init(bar1, ARRIVES); }
    if (t < DIM) { h_f[0][t] = 0.0f; h_f[1][t] = 0.0f; }
    __syncthreads();
    cluster_sync();   // barriers initialized before any remote traffic

    // Remote addrs (k==0 senders): peer's h_f[b][dim], peer's mbars[b]
    uint32_t rh0 = mapa_u32(smem_u32(&h_f[0][dim]), peer);
    uint32_t rh1 = mapa_u32(smem_u32(&h_f[1][dim]), peer);
    uint32_t rb0 = mapa_u32(bar0, peer);
    uint32_t rb1 = mapa_u32(bar1, peer);

    float c = 0.0f;                 // redundant per 4-lane group
    float hmax = -3.0e38f;
    float xg_next = g_xg[grow];     // step 0's input contribution

    for (int step = 0; step < SEQ; step++) {
        int buf = step & 1;
        // wait for peer's half of h(step-1); step 0 reads zeroed buffer
        if (step > 0)
            mbar_wait_parity_cluster(buf ? bar1 : bar0, ((step - 1) >> 1) & 1);

        u64 a0 = pack2(xg_next, 0.0f);
        u64 a1 = pack2(0.0f, 0.0f);
        u64 a2 = a1, a3 = a1;
        int nstep = min(step + 1, SEQ - 1);
        xg_next = __ldg(&g_xg[(size_t)nstep * GATES + grow]);

        const ulonglong2* hh = reinterpret_cast<const ulonglong2*>(h_f[buf]);
#pragma unroll
        for (int q = 0; q < 16; q++) {
            ulonglong2 p0 = hh[2 * q];       // broadcast LDS
            ulonglong2 p1 = hh[2 * q + 1];
            a0 = fma2(w2[4 * q + 0], p0.x, a0);
            a1 = fma2(w2[4 * q + 1], p0.y, a1);
            a2 = fma2(w2[4 * q + 2], p1.x, a2);
            a3 = fma2(w2[4 * q + 3], p1.y, a3);
        }
        float v = hsum2(add2(add2(a0, a1), add2(a2, a3)));
        // unified activation: sigma(x) or tanh(x)=2*sigma(2x)-1, one MUFU path
        float xx = is_g ? 2.0f * v : v;
        float s  = 1.0f / (1.0f + __expf(-xx));
        float gv = is_g ? fmaf(2.0f, s, -1.0f) : s;

        // gather this dim's 4 gates via warp shuffles (same 4-lane group)
        float iv = __shfl_sync(0xffffffffu, gv, base + 0, 32);
        float fv = __shfl_sync(0xffffffffu, gv, base + 1, 32);
        float gg = __shfl_sync(0xffffffffu, gv, base + 2, 32);
        float ov = __shfl_sync(0xffffffffu, gv, base + 3, 32);

        c = fmaf(fv, c, iv * gg);            // redundant in 4 lanes
        float h = ov * fast_tanh(c);
        hmax = fmaxf(hmax, h);

        int nb = buf ^ 1;                    // next step's buffer
        if (k == 0) {
            h_f[nb][dim] = h;                          // local own half
            st_cluster_f32(nb ? rh1 : rh0, h);         // ship to peer
            mbar_arrive_release_cluster(nb ? rb1 : rb0); // signal peer
        }
        __syncthreads();                     // local own-half h visible
    }

    if (k == 0) out[dim] = hmax;             // each CTA writes its 64 dims
    cluster_sync();   // keep peer smem alive until all remote ops drained
}

// ---------------------------------------------------------------------------
extern "C" void kernel_launch(void* const* d_in, const int* in_sizes, int n_in,
                              void* d_out, int out_size) {
    const float* embs  = (const float*)d_in[0];
    const int*   pos   = (const int*)  d_in[1];
    const float* W_exp = (const float*)d_in[2];
    const float* b_exp = (const float*)d_in[3];
    const float* W_ih  = (const float*)d_in[4];
    const float* W_hh  = (const float*)d_in[5];
    const float* b_ih  = (const float*)d_in[6];
    const float* b_hh  = (const float*)d_in[7];
    float* out = (float*)d_out;

    k_expert<<<SEQ, DIM>>>(embs, pos, W_exp, b_exp);
    k_inproj<<<SEQ / TOK_PER_BLK, GATES>>>(W_ih, b_ih, b_hh);
    k_lstm2<<<2, LSTM_THREADS>>>(W_hh, out);
}